// round 1
// baseline (speedup 1.0000x reference)
#include <cuda_runtime.h>
#include <cuda_bf16.h>
#include <math.h>

#define Hh 1024
#define Ww 1024
#define Nn 32
#define NCOLS (Nn * Ww)          // 32768 columns (one per (n,w))
#define NELEM (Nn * Hh * Ww)     // 33554432 elements
#define NCHUNK (Hh / 32)         // 32 bit-chunks per column

// Scratch (device globals: allocation-free per harness rules)
__device__ unsigned short g_dfwd[NELEM];        // 64 MB forward distances
__device__ unsigned int   g_bits[NELEM / 32];   // 4 MB predbin bitmask, layout [hchunk][col]
__device__ double             g_bce;
__device__ unsigned long long g_total;
__device__ unsigned long long g_cnt;

__global__ void init_kernel() {
    g_bce = 0.0;
    g_total = 0ULL;
    g_cnt = 0ULL;
}

// Forward pass: per-column grassfire down-sweep, BCE partial sums, count, predbin bits.
__global__ __launch_bounds__(128) void fwd_kernel(const float* __restrict__ pred,
                                                  const float* __restrict__ targ) {
    int col = blockIdx.x * blockDim.x + threadIdx.x;   // 0..NCOLS-1 (exact multiple)
    int n = col >> 10;
    int w = col & 1023;
    unsigned base = (unsigned)n * (Hh * Ww) + (unsigned)w;

    int carry = 1 << 20;   // "inf": first row unchanged
    float bce = 0.0f;
    unsigned cnt = 0;

    for (int hc = 0; hc < NCHUNK; ++hc) {
        unsigned bits = 0;
#pragma unroll
        for (int j = 0; j < 32; ++j) {
            unsigned h = (unsigned)(hc * 32 + j);
            unsigned idx = base + h * Ww;
            float t = targ[idx];
            float p = pred[idx];

            int a = (t == 1.0f) ? 0 : 1024;
            carry = min(a, carry + 1);
            g_dfwd[idx] = (unsigned short)carry;

            unsigned pb = (p > 0.0f) ? 1u : 0u;
            bits |= pb << j;
            cnt += pb & ((t != 1.0f) ? 1u : 0u);   // count of (penalty != 0)

            // numerically stable BCE-with-logits
            bce += fmaxf(p, 0.0f) - p * t + log1pf(expf(-fabsf(p)));
        }
        g_bits[hc * NCOLS + col] = bits;
    }

    // block reduction: bce (float) + cnt (u32)
#pragma unroll
    for (int o = 16; o > 0; o >>= 1) {
        bce += __shfl_down_sync(0xffffffffu, bce, o);
        cnt += __shfl_down_sync(0xffffffffu, cnt, o);
    }
    __shared__ float    sb[4];
    __shared__ unsigned sc[4];
    int wid = threadIdx.x >> 5, lid = threadIdx.x & 31;
    if (lid == 0) { sb[wid] = bce; sc[wid] = cnt; }
    __syncthreads();
    if (threadIdx.x == 0) {
        float tb = sb[0] + sb[1] + sb[2] + sb[3];
        unsigned tc = sc[0] + sc[1] + sc[2] + sc[3];
        atomicAdd(&g_bce, (double)tb);
        atomicAdd(&g_cnt, (unsigned long long)tc);
    }
}

// Backward pass: up-sweep min over forward distances, accumulate total = sum(predbin * dist).
__global__ __launch_bounds__(128) void bwd_kernel() {
    int col = blockIdx.x * blockDim.x + threadIdx.x;
    int n = col >> 10;
    int w = col & 1023;
    unsigned base = (unsigned)n * (Hh * Ww) + (unsigned)w;

    int carry = 1 << 20;
    unsigned total = 0;   // per-thread max = 1024*1024 = 2^20, fits u32

    for (int hc = NCHUNK - 1; hc >= 0; --hc) {
        unsigned bits = g_bits[hc * NCOLS + col];
#pragma unroll
        for (int j = 31; j >= 0; --j) {
            unsigned h = (unsigned)(hc * 32 + j);
            unsigned idx = base + h * Ww;
            int dv = (int)g_dfwd[idx];
            carry = min(dv, carry + 1);
            total += ((bits >> j) & 1u) * (unsigned)carry;
        }
    }

#pragma unroll
    for (int o = 16; o > 0; o >>= 1)
        total += __shfl_down_sync(0xffffffffu, total, o);
    __shared__ unsigned st[4];
    int wid = threadIdx.x >> 5, lid = threadIdx.x & 31;
    if (lid == 0) st[wid] = total;
    __syncthreads();
    if (threadIdx.x == 0) {
        unsigned tt = st[0] + st[1] + st[2] + st[3];
        atomicAdd(&g_total, (unsigned long long)tt);
    }
}

__global__ void fin_kernel(float* out) {
    double bce = g_bce / (double)NELEM;
    unsigned long long tot = g_total;
    unsigned long long cnt = g_cnt;
    double border = (tot == 0ULL) ? 0.0
                                  : ((double)tot / (double)(cnt > 1ULL ? cnt : 1ULL));
    out[0] = (float)(bce + sqrt(border));
}

extern "C" void kernel_launch(void* const* d_in, const int* in_sizes, int n_in,
                              void* d_out, int out_size) {
    const float* pred = (const float*)d_in[0];   // predictions
    const float* targ = (const float*)d_in[1];   // targets
    float* out = (float*)d_out;

    init_kernel<<<1, 1>>>();
    fwd_kernel<<<NCOLS / 128, 128>>>(pred, targ);
    bwd_kernel<<<NCOLS / 128, 128>>>();
    fin_kernel<<<1, 1>>>(out);
}

// round 2
// speedup vs baseline: 5.4902x; 5.4902x over previous
#include <cuda_runtime.h>
#include <cuda_bf16.h>
#include <math.h>

#define Hh 1024
#define Ww 1024
#define Nn 32
#define NCOLS (Nn * Ww)          // 32768 columns, one per (n,w)
#define NELEM (Nn * Hh * Ww)     // 33554432
#define NSEG 16                  // segments per column
#define SLEN 64                  // rows per segment
#define NTHREADS_SEG (NCOLS * NSEG)   // 524288
#define BIG (1 << 20)

// Scratch (__device__ globals: allocation-free per harness rules)
__device__ unsigned g_tbits[NSEG * 2 * NCOLS];   // 4 MB target bitmask  [seg*2+wch][col]
__device__ unsigned g_pbits[NSEG * 2 * NCOLS];   // 4 MB predbin bitmask
__device__ int      g_A[NSEG * NCOLS];           // 2 MB fwd seg aggregate
__device__ int      g_B[NSEG * NCOLS];           // 2 MB bwd seg aggregate
__device__ int      g_cf[NSEG * NCOLS];          // 2 MB fwd carry-in per seg
__device__ int      g_cb[NSEG * NCOLS];          // 2 MB bwd carry-in per seg
__device__ double             g_bce;
__device__ unsigned long long g_total;
__device__ unsigned long long g_cnt;

__global__ void init_kernel() {
    g_bce = 0.0; g_total = 0ULL; g_cnt = 0ULL;
}

// K1: stream pred+targ once. Per (col, seg of 64 rows): BCE partial, count partial,
// target/predbin bitmasks, and fwd/bwd min-plus segment aggregates.
__global__ __launch_bounds__(256) void k1_kernel(const float* __restrict__ pred,
                                                 const float* __restrict__ targ) {
    unsigned gid = blockIdx.x * 256u + threadIdx.x;
    unsigned col = gid & (NCOLS - 1);
    unsigned seg = gid >> 15;
    unsigned base = (col >> 10) * (Hh * Ww) + (col & 1023) + seg * SLEN * Ww;

    int A = BIG;                 // scan value at segment end (carry-out w/ inf carry-in)
    int B = BIG;                 // min_j (a_j + j_offset)  (bwd carry source)
    float bce = 0.0f;
    unsigned cnt = 0;

    for (int wch = 0; wch < 2; ++wch) {
        unsigned tw = 0, pw = 0;
#pragma unroll
        for (int j = 0; j < 32; ++j) {
            int jo = wch * 32 + j;
            unsigned idx = base + (unsigned)jo * Ww;
            float t = targ[idx];
            float p = pred[idx];

            unsigned isT = (t == 1.0f) ? 1u : 0u;
            unsigned pb  = (p > 0.0f) ? 1u : 0u;
            tw |= isT << j;
            pw |= pb  << j;
            cnt += pb & (isT ^ 1u);

            int a = isT ? 0 : 1024;
            A = min(a, A + 1);
            B = min(B, a + jo);

            bce += fmaxf(p, 0.0f) - p * t + __logf(1.0f + __expf(-fabsf(p)));
        }
        g_tbits[(seg * 2 + wch) * NCOLS + col] = tw;
        g_pbits[(seg * 2 + wch) * NCOLS + col] = pw;
    }
    g_A[seg * NCOLS + col] = A;
    g_B[seg * NCOLS + col] = B;

    // block reduce bce + cnt
#pragma unroll
    for (int o = 16; o > 0; o >>= 1) {
        bce += __shfl_down_sync(0xffffffffu, bce, o);
        cnt += __shfl_down_sync(0xffffffffu, cnt, o);
    }
    __shared__ float    sb[8];
    __shared__ unsigned sc[8];
    int wid = threadIdx.x >> 5, lid = threadIdx.x & 31;
    if (lid == 0) { sb[wid] = bce; sc[wid] = cnt; }
    __syncthreads();
    if (threadIdx.x == 0) {
        float tb = 0.0f; unsigned tc = 0;
#pragma unroll
        for (int i = 0; i < 8; ++i) { tb += sb[i]; tc += sc[i]; }
        atomicAdd(&g_bce, (double)tb);
        atomicAdd(&g_cnt, (unsigned long long)tc);
    }
}

// K2: per-column carry propagation across segments (both directions).
__global__ __launch_bounds__(256) void k2_kernel() {
    unsigned col = blockIdx.x * 256u + threadIdx.x;   // 0..NCOLS-1
    int c = BIG;
#pragma unroll
    for (int s = 0; s < NSEG; ++s) {
        g_cf[s * NCOLS + col] = c;
        int A = g_A[s * NCOLS + col];
        c = min(A + 1, c + SLEN);
    }
    c = BIG;
#pragma unroll
    for (int s = NSEG - 1; s >= 0; --s) {
        g_cb[s * NCOLS + col] = c;
        int B = g_B[s * NCOLS + col];
        c = min(B + 1, c + SLEN);
    }
}

// K3: reconstruct a from bits, local fwd+bwd scans with carries, accumulate total.
__global__ __launch_bounds__(256) void k3_kernel() {
    unsigned gid = blockIdx.x * 256u + threadIdx.x;
    unsigned col = gid & (NCOLS - 1);
    unsigned seg = gid >> 15;

    unsigned t0 = g_tbits[(seg * 2 + 0) * NCOLS + col];
    unsigned t1 = g_tbits[(seg * 2 + 1) * NCOLS + col];
    unsigned p0 = g_pbits[(seg * 2 + 0) * NCOLS + col];
    unsigned p1 = g_pbits[(seg * 2 + 1) * NCOLS + col];
    int cf = g_cf[seg * NCOLS + col];
    int cb = g_cb[seg * NCOLS + col];

    int farr[SLEN];
    int f = cf - 1;
#pragma unroll
    for (int i = 0; i < SLEN; ++i) {
        unsigned bit = (i < 32) ? ((t0 >> i) & 1u) : ((t1 >> (i - 32)) & 1u);
        int a = bit ? 0 : 1024;
        f = min(a, f + 1);
        farr[i] = f;
    }
    int b = cb - 1;
    unsigned tot = 0;
#pragma unroll
    for (int i = SLEN - 1; i >= 0; --i) {
        unsigned tb = (i < 32) ? ((t0 >> i) & 1u) : ((t1 >> (i - 32)) & 1u);
        unsigned pb = (i < 32) ? ((p0 >> i) & 1u) : ((p1 >> (i - 32)) & 1u);
        int a = tb ? 0 : 1024;
        b = min(a, b + 1);
        int d = min(farr[i], b);
        tot += pb ? (unsigned)d : 0u;
    }

#pragma unroll
    for (int o = 16; o > 0; o >>= 1)
        tot += __shfl_down_sync(0xffffffffu, tot, o);
    __shared__ unsigned st[8];
    int wid = threadIdx.x >> 5, lid = threadIdx.x & 31;
    if (lid == 0) st[wid] = tot;
    __syncthreads();
    if (threadIdx.x == 0) {
        unsigned tt = 0;
#pragma unroll
        for (int i = 0; i < 8; ++i) tt += st[i];
        atomicAdd(&g_total, (unsigned long long)tt);
    }
}

__global__ void fin_kernel(float* out) {
    double bce = g_bce / (double)NELEM;
    unsigned long long tot = g_total;
    unsigned long long cnt = g_cnt;
    double border = (tot == 0ULL) ? 0.0
                                  : ((double)tot / (double)(cnt > 1ULL ? cnt : 1ULL));
    out[0] = (float)(bce + sqrt(border));
}

extern "C" void kernel_launch(void* const* d_in, const int* in_sizes, int n_in,
                              void* d_out, int out_size) {
    const float* pred = (const float*)d_in[0];
    const float* targ = (const float*)d_in[1];
    float* out = (float*)d_out;

    init_kernel<<<1, 1>>>();
    k1_kernel<<<NTHREADS_SEG / 256, 256>>>(pred, targ);
    k2_kernel<<<NCOLS / 256, 256>>>();
    k3_kernel<<<NTHREADS_SEG / 256, 256>>>();
    fin_kernel<<<1, 1>>>(out);
}